// round 13
// baseline (speedup 1.0000x reference)
#include <cuda_runtime.h>
#include <cuda_fp16.h>
#include <mma.h>
#include <math.h>

using namespace nvcuda;

#define NN 10000
#define UU 64
#define EE 160000
#define DD 66
#define BN 160000   // B*N
#define BD 1056     // B*D
#define CAP 96      // per-row edge capacity (lambda=16, P(>=96) ~ 1e-43)

// gates GEMM tiles: M64 x N128 x K80(pad of 66)
#define LDA_G 88
#define LDB_G 136
#define LDO_G 132
#define KP_G 80
#define SA_G_BYTES (64 * LDA_G * 2)                      // 11264 (preserved through epilogue)
#define SB_G_BYTES (KP_G * LDB_G * 2)                    // 21760 (sOut 32xLDO_G*4=16896 aliases)
#define SMEM_G (SA_G_BYTES + SB_G_BYTES + 128 * 4)       // 33536 -> 6 CTAs/SM
// cand GEMM tiles: M64 x N64 x K144(pad of 132)
#define LDA_C 152
#define LDB_C 72
#define LDO_C 68
#define KP_C 144
#define CATS 136    // padded g_cat row stride (halves) = 272B = 17 x 16B
#define GEMM_REG_C 40192   // max(64*LDA_C*2 + KP_C*LDB_C*2 = 40192, 64*LDO_C*4 = 17408)
#define SMEM_C (GEMM_REG_C + 64 * 4)

#define SPMM_LANES 132     // 16B per lane per row (1056 halves = 132 x uint4)

// ---------------- scratch (device globals: allocation-free rule; zero-initialized) ----
__device__ __align__(16) __half g_x0h[(size_t)NN * BD];    // (n,b,d) fp16: inputs ++ r*hx
__device__ __align__(16) __half g_cat[(size_t)BN * CATS];  // (row, 2d+m) + 4-half zero pad
__device__ __align__(16) __half g_uh [(size_t)BN * UU];    // update gate fp16
__device__ __align__(16) __half g_wfch[KP_G * 128];        // W_fc fp16; rows 66..79 stay 0
__device__ __align__(16) __half g_wgh [KP_C * 64];         // W_g fp16; rows 132..143 stay 0
__device__ int    g_cnt[NN];                               // zero on entry (restored by k_cand)
__device__ int    g_scol[NN * CAP];
__device__ float  g_sval[NN * CAP];

__device__ __forceinline__ float fsigmoid(float z) { return 1.f / (1.f + __expf(-z)); }
__device__ __forceinline__ float ftanh(float x) {
    float y; asm("tanh.approx.f32 %0, %1;" : "=f"(y) : "f"(x)); return y;
}
__device__ __forceinline__ void cp_async16(void* sdst, const void* gsrc) {
    unsigned s = (unsigned)__cvta_generic_to_shared(sdst);
    asm volatile("cp.async.cg.shared.global [%0], [%1], 16;" :: "r"(s), "l"(gsrc));
}
__device__ __forceinline__ void cp_commit() { asm volatile("cp.async.commit_group;"); }
__device__ __forceinline__ void cp_wait0()  { asm volatile("cp.async.wait_group 0;" ::: "memory"); }

// ---------------- kernel 0a: fp16 weight conversion (33 blocks, main stream) ----------
__global__ void k_wcvt(const float* __restrict__ Wfc, const float* __restrict__ Wg) {
    int e = blockIdx.x * blockDim.x + threadIdx.x;
    if (e < 4224) {                     // W_fc: 66*128 = 8448 floats = 4224 float2
        float2 w = ((const float2*)Wfc)[e];
        ((__half2*)g_wfch)[e] = __floats2half2_rn(w.x, w.y);
    } else if (e < 8448) {              // W_g: 132*64 floats
        int i = e - 4224;
        float2 w = ((const float2*)Wg)[i];
        ((__half2*)g_wgh)[i] = __floats2half2_rn(w.x, w.y);
    }
}

// ---------------- kernel 0b: edge scatter, 4 edges/thread (side stream) ---------------
__global__ void k_scatter(const int* __restrict__ rows, const int* __restrict__ cols,
                          const float* __restrict__ vals) {
    int gid = blockIdx.x * blockDim.x + threadIdx.x;
    if (gid < EE / 4) {
        int4   r4 = ((const int4*)rows)[gid];
        int4   c4 = ((const int4*)cols)[gid];
        float4 v4 = ((const float4*)vals)[gid];
        int rr[4] = {r4.x, r4.y, r4.z, r4.w};
        int cc[4] = {c4.x, c4.y, c4.z, c4.w};
        float vv[4] = {v4.x, v4.y, v4.z, v4.w};
#pragma unroll
        for (int e = 0; e < 4; ++e) {
            int slot = atomicAdd(&g_cnt[rr[e]], 1);
            if (slot < CAP) {
                g_scol[rr[e] * CAP + slot] = cc[e];
                g_sval[rr[e] * CAP + slot] = vv[e];
            }
        }
    }
}

// ---------------- kernel 1: gates via HMMA; two-phase epilogue (small smem) ----------
__global__ void __launch_bounds__(256) k_gates(const float* __restrict__ inputs,
                                               const float* __restrict__ hx,
                                               const float* __restrict__ bfc) {
    extern __shared__ char smraw[];
    __half* sA   = (__half*)smraw;                        // 64 x LDA_G (preserved)
    __half* sB   = (__half*)(smraw + SA_G_BYTES);         // KP_G x LDB_G
    float*  sOut = (float*)(smraw + SA_G_BYTES);          // 32 x LDO_G (aliases sB)
    float*  sBias = (float*)(smraw + SA_G_BYTES + SB_G_BYTES);   // 128

    int tid = threadIdx.x;
    int r0 = blockIdx.x * 64;

    // sB via cp.async from pre-converted g_wfch (80 rows x 16 chunks of 16B)
#pragma unroll
    for (int i = tid; i < KP_G * 16; i += 256) {
        int k = i >> 4, c = i & 15;
        cp_async16(sB + k * LDB_G + c * 8, g_wfch + k * 128 + c * 8);
    }
    cp_commit();

    // sA rows with [inputs(2) | hx(64)] fp16; pad cols 66..79
    for (int i = tid; i < 1024; i += 256) {
        int r = i >> 4, q = i & 15;
        float4 h = ((const float4*)hx)[(size_t)(r0 + r) * 16 + q];
        int off = r * LDA_G + 2 + q * 4;
        *(__half2*)(sA + off)     = __floats2half2_rn(h.x, h.y);
        *(__half2*)(sA + off + 2) = __floats2half2_rn(h.z, h.w);
    }
    if (tid < 64) {
        float2 xin = ((const float2*)inputs)[r0 + tid];
        *(__half2*)(sA + tid * LDA_G) = __floats2half2_rn(xin.x, xin.y);
        __half2 zz = __half2half2(__float2half(0.f));
#pragma unroll
        for (int k = 66; k < KP_G; k += 2) *(__half2*)(sA + tid * LDA_G + k) = zz;
    }
    if (tid < 128) sBias[tid] = bfc[tid];
    cp_wait0();
    __syncthreads();

    // 8 warps: warp (wm, wn): m-tile wm (0..3), n-tiles wn*4 .. wn*4+3
    int wid = tid >> 5;
    int wm = wid & 3, wn = wid >> 2;
    wmma::fragment<wmma::accumulator, 16, 16, 16, float> c[4];
#pragma unroll
    for (int j = 0; j < 4; ++j) wmma::fill_fragment(c[j], 0.f);
#pragma unroll
    for (int k = 0; k < KP_G / 16; ++k) {
        wmma::fragment<wmma::matrix_a, 16, 16, 16, __half, wmma::row_major> a;
        wmma::load_matrix_sync(a, sA + wm * 16 * LDA_G + k * 16, LDA_G);
#pragma unroll
        for (int j = 0; j < 4; ++j) {
            wmma::fragment<wmma::matrix_b, 16, 16, 16, __half, wmma::row_major> b;
            wmma::load_matrix_sync(b, sB + k * 16 * LDB_G + (wn * 4 + j) * 16, LDB_G);
            wmma::mma_sync(c[j], a, b, c[j]);
        }
    }

    // two-phase epilogue: phase p handles rows p*32 .. p*32+31 (sOut = 32 rows)
#pragma unroll
    for (int p = 0; p < 2; ++p) {
        __syncthreads();   // sOut region free (sB dead after MMA / prev phase done)
        if ((wm >> 1) == p) {
            int rloc = (wm & 1) * 16;
#pragma unroll
            for (int j = 0; j < 4; ++j)
                wmma::store_matrix_sync(sOut + rloc * LDO_G + (wn * 4 + j) * 16, c[j],
                                        LDO_G, wmma::mem_row_major);
        }
        __syncthreads();
        for (int i = tid; i < 1024; i += 256) {
            int rl = i >> 5, q = i & 31;
            int col = q * 4;
            int r = p * 32 + rl;
            int row = r0 + r;
            float4 z = *(float4*)(sOut + rl * LDO_G + col);
            z.x = fsigmoid(z.x + sBias[col + 0]);
            z.y = fsigmoid(z.y + sBias[col + 1]);
            z.z = fsigmoid(z.z + sBias[col + 2]);
            z.w = fsigmoid(z.w + sBias[col + 3]);
            if (q < 16) {
                // hx fp16 in sA at halves offset ≡ 2 mod 4 -> two half2 loads
                __half2 h01 = *(__half2*)(sA + r * LDA_G + 2 + col);
                __half2 h23 = *(__half2*)(sA + r * LDA_G + 2 + col + 2);
                float2 ha = __half22float2(h01);
                float2 hb = __half22float2(h23);
                int n = row % NN, b = row / NN;
                size_t base = (size_t)n * BD + b * DD + 2 + col;
                *(__half2*)(g_x0h + base)     = __floats2half2_rn(z.x * ha.x, z.y * ha.y);
                *(__half2*)(g_x0h + base + 2) = __floats2half2_rn(z.z * hb.x, z.w * hb.y);
            } else {
                __half2 a = __floats2half2_rn(z.x, z.y);
                __half2 b2 = __floats2half2_rn(z.z, z.w);
                uint2 uv;
                uv.x = *(unsigned*)&a; uv.y = *(unsigned*)&b2;
                ((uint2*)g_uh)[(size_t)row * 16 + (q - 16)] = uv;
            }
        }
    }
    // x0h[n, b, 0:2] = inputs (fp16, from sA — row start is 4B-aligned half2)
    if (tid < 64) {
        int row = r0 + tid;
        int n = row % NN, b = row / NN;
        *(__half2*)(g_x0h + (size_t)n * BD + b * DD) = *(__half2*)(sA + tid * LDA_G);
    }
}

// ---------------- kernel 2: SpMM (HFMA2, 16B lanes, 2 nodes/block) -------------------
// 264 threads = 2 groups x 132 lanes; lane owns 16B (8 halves) of the 2112B row.
__global__ void __launch_bounds__(264) k_spmm() {
    __shared__ int     s_col[2][CAP];
    __shared__ __half2 s_val[2][CAP];     // pre-splatted fp16 edge values
    int n0 = blockIdx.x * 2;
    int tid = threadIdx.x;
    int g = (tid >= SPMM_LANES) ? 1 : 0;
    int l = tid - g * SPMM_LANES;         // 0..131
    int n = n0 + g;
    int cnt = min(g_cnt[n], CAP);
    if (l < cnt) {
        s_col[g][l] = g_scol[n * CAP + l];
        s_val[g][l] = __half2half2(__float2half_rn(g_sval[n * CAP + l]));
    }
    __syncthreads();

    const uint4* x16 = (const uint4*)g_x0h;   // row stride = 132 uint4
    __half2 acc[4];
#pragma unroll
    for (int e = 0; e < 4; ++e) acc[e] = __half2half2(__float2half(0.f));
    for (int i = 0; i < cnt; ++i) {
        __half2 v = s_val[g][i];
        int     c = s_col[g][i];
        uint4 raw = x16[(size_t)c * SPMM_LANES + l];
        acc[0] = __hfma2(*(__half2*)&raw.x, v, acc[0]);
        acc[1] = __hfma2(*(__half2*)&raw.y, v, acc[1]);
        acc[2] = __hfma2(*(__half2*)&raw.z, v, acc[2]);
        acc[3] = __hfma2(*(__half2*)&raw.w, v, acc[3]);
    }

    // own x0 slice (8 halves) + x1 (8 halves) -> interleave into g_cat
    uint4 own = x16[(size_t)n * SPMM_LANES + l];
    __half x0e[8], x1e[8];
    *(__half2*)&x0e[0] = *(__half2*)&own.x;
    *(__half2*)&x0e[2] = *(__half2*)&own.y;
    *(__half2*)&x0e[4] = *(__half2*)&own.z;
    *(__half2*)&x0e[6] = *(__half2*)&own.w;
#pragma unroll
    for (int e = 0; e < 4; ++e) *(__half2*)&x1e[e * 2] = acc[e];

    __half2* cat2 = (__half2*)g_cat;
    int j0 = l * 8;
    int b = j0 / DD;
    int d = j0 - b * DD;
#pragma unroll
    for (int e = 0; e < 8; ++e) {
        size_t row = (size_t)b * NN + n;
        cat2[row * (CATS / 2) + d] = __halves2half2(x0e[e], x1e[e]);
        if (++d == DD) { d = 0; ++b; }
    }
    // zero 4-half row pads (halves 132..135): 2 nodes x 16 batches
    if (tid < 32) {
        int gg = tid >> 4, bb = tid & 15;
        ((uint2*)g_cat)[((size_t)bb * NN + (n0 + gg)) * (CATS / 4) + 33] = make_uint2(0u, 0u);
    }
}

// ---------------- kernel 3: candidate GEMM via HMMA (+tanh) and GRU combine ----------
__global__ void __launch_bounds__(256) k_cand(const float* __restrict__ hx,
                                              const float* __restrict__ bg,
                                              float* __restrict__ out) {
    extern __shared__ char smraw[];
    __half* sA   = (__half*)smraw;                    // 64 x LDA_C
    __half* sB   = sA + 64 * LDA_C;                   // KP_C x LDB_C
    float*  sOut = (float*)smraw;                     // 64 x LDO_C (aliases sA/sB)
    float*  sBias = (float*)(smraw + GEMM_REG_C);     // 64

    int tid = threadIdx.x;
    int r0 = blockIdx.x * 64;

    // restore g_cnt = 0 for the next call (g_cnt already consumed by k_spmm)
    if (tid < 4) g_cnt[blockIdx.x * 4 + tid] = 0;

    // sB via cp.async from g_wgh (144 rows x 8 chunks of 16B)
#pragma unroll
    for (int i = tid; i < KP_C * 8; i += 256) {
        int k = i >> 3, c = i & 7;
        cp_async16(sB + k * LDB_C + c * 8, g_wgh + k * 64 + c * 8);
    }
    // sA via cp.async from padded g_cat (64 rows x 17 chunks of 16B)
#pragma unroll
    for (int i = tid; i < 64 * 17; i += 256) {
        int r = i / 17, dp = i - r * 17;
        cp_async16(sA + r * LDA_C + dp * 8, g_cat + (size_t)(r0 + r) * CATS + dp * 8);
    }
    cp_commit();
    if (tid < 64) {
        *(uint4*)(sA + tid * LDA_C + 136) = make_uint4(0u, 0u, 0u, 0u);  // k 136..143
        sBias[tid] = bg[tid];
    }
    cp_wait0();
    __syncthreads();

    // 8 warps: warp (wm, wn2): m-tile wm, n-tiles wn2*2 + {0,1}
    int wid = tid >> 5;
    int wm = wid & 3, wn2 = wid >> 2;
    wmma::fragment<wmma::accumulator, 16, 16, 16, float> c[2];
#pragma unroll
    for (int j = 0; j < 2; ++j) wmma::fill_fragment(c[j], 0.f);
#pragma unroll
    for (int k = 0; k < KP_C / 16; ++k) {
        wmma::fragment<wmma::matrix_a, 16, 16, 16, __half, wmma::row_major> a;
        wmma::load_matrix_sync(a, sA + wm * 16 * LDA_C + k * 16, LDA_C);
#pragma unroll
        for (int j = 0; j < 2; ++j) {
            wmma::fragment<wmma::matrix_b, 16, 16, 16, __half, wmma::row_major> b;
            wmma::load_matrix_sync(b, sB + k * 16 * LDB_C + (wn2 * 2 + j) * 16, LDB_C);
            wmma::mma_sync(c[j], a, b, c[j]);
        }
    }
    __syncthreads();   // sOut aliases sA/sB
#pragma unroll
    for (int j = 0; j < 2; ++j)
        wmma::store_matrix_sync(sOut + wm * 16 * LDO_C + (wn2 * 2 + j) * 16, c[j],
                                LDO_C, wmma::mem_row_major);
    __syncthreads();

    // epilogue: tanh.approx + GRU combine, vectorized float4
    for (int i = tid; i < 1024; i += 256) {
        int r = i >> 4, q = i & 15;
        int col = q * 4;
        int row = r0 + r;
        float4 z = *(float4*)(sOut + r * LDO_C + col);
        z.x = ftanh(z.x + sBias[col + 0]);
        z.y = ftanh(z.y + sBias[col + 1]);
        z.z = ftanh(z.z + sBias[col + 2]);
        z.w = ftanh(z.w + sBias[col + 3]);
        size_t o = (size_t)row * 16 + q;
        uint2 uv = ((const uint2*)g_uh)[o];
        float2 ua = __half22float2(*(__half2*)&uv.x);
        float2 ub = __half22float2(*(__half2*)&uv.y);
        float4 h4 = ((const float4*)hx)[o];
        float4 res;
        res.x = ua.x * h4.x + (1.f - ua.x) * z.x;
        res.y = ua.y * h4.y + (1.f - ua.y) * z.y;
        res.z = ub.x * h4.z + (1.f - ub.x) * z.z;
        res.w = ub.y * h4.w + (1.f - ub.y) * z.w;
        ((float4*)out)[o] = res;
    }
}

// ---------------- launcher: fork-join — scatter overlaps wcvt+gates ------------------
extern "C" void kernel_launch(void* const* d_in, const int* in_sizes, int n_in,
                              void* d_out, int out_size) {
    (void)in_sizes; (void)n_in; (void)out_size;
    const float* inputs = (const float*)d_in[0];
    const float* hx     = (const float*)d_in[1];
    const int*   rows   = (const int*)d_in[2];
    const int*   cols   = (const int*)d_in[3];
    const float* vals   = (const float*)d_in[4];
    const float* Wfc    = (const float*)d_in[5];
    const float* bfc    = (const float*)d_in[6];
    const float* Wg     = (const float*)d_in[7];
    const float* bg     = (const float*)d_in[8];
    float* out = (float*)d_out;

    static cudaStream_t s1 = nullptr;
    static cudaEvent_t evFork = nullptr, evScat = nullptr;
    if (s1 == nullptr) {   // one-time handle creation (no device memory involved)
        cudaStreamCreateWithFlags(&s1, cudaStreamNonBlocking);
        cudaEventCreateWithFlags(&evFork, cudaEventDisableTiming);
        cudaEventCreateWithFlags(&evScat, cudaEventDisableTiming);
        cudaFuncSetAttribute(k_gates, cudaFuncAttributeMaxDynamicSharedMemorySize, SMEM_G);
        cudaFuncSetAttribute(k_cand,  cudaFuncAttributeMaxDynamicSharedMemorySize, SMEM_C);
    }

    // fork: side stream runs edge scatter concurrently with weight cvt + gates
    cudaEventRecord(evFork, 0);
    cudaStreamWaitEvent(s1, evFork, 0);
    k_scatter<<<(EE / 4 + 255) / 256, 256, 0, s1>>>(rows, cols, vals);
    cudaEventRecord(evScat, s1);

    k_wcvt<<<33, 256>>>(Wfc, Wg);
    k_gates<<<BN / 64, 256, SMEM_G>>>(inputs, hx, bfc);

    // join: spmm needs both gates (x0h) and scatter (edge lists)
    cudaStreamWaitEvent(0, evScat, 0);
    k_spmm<<<NN / 2, 264>>>();
    k_cand<<<BN / 64, 256, SMEM_C>>>(hx, bg, out);
}

// round 14
// speedup vs baseline: 1.1008x; 1.1008x over previous
#include <cuda_runtime.h>
#include <cuda_fp16.h>
#include <mma.h>
#include <math.h>

using namespace nvcuda;

#define NN 10000
#define UU 64
#define EE 160000
#define DD 66
#define BN 160000   // B*N
#define BD 1056     // B*D
#define CAP 96      // per-row edge capacity (lambda=16, P(>=96) ~ 1e-43)

// gates GEMM tiles: M64 x N128 x K80(pad of 66)
#define LDA_G 88
#define LDB_G 136
#define LDO_G 132
#define KP_G 80
#define SA_G_BYTES (64 * LDA_G * 2)                      // 11264 (preserved through epilogue)
#define SB_G_BYTES (KP_G * LDB_G * 2)                    // 21760 (sOut 32xLDO_G*4=16896 aliases)
#define SMEM_G (SA_G_BYTES + SB_G_BYTES + 128 * 4)       // 33536 -> 6 CTAs/SM
// cand GEMM tiles: M64 x N64 x K144(pad of 132)
#define LDA_C 152
#define LDB_C 72
#define LDO_C 68
#define KP_C 144
#define CATS 136    // padded g_cat row stride (halves) = 272B = 17 x 16B
#define GEMM_REG_C 40192   // max(64*LDA_C*2 + KP_C*LDB_C*2 = 40192, 64*LDO_C*4 = 17408)
#define SMEM_C (GEMM_REG_C + 64 * 4)

// ---------------- scratch (device globals: allocation-free rule; zero-initialized) ----
__device__ __align__(16) __half g_x0h[(size_t)NN * BD];    // (n,b,d) fp16: inputs ++ r*hx
__device__ __align__(16) __half g_cat[(size_t)BN * CATS];  // (row, 2d+m) + 4-half zero pad
__device__ __align__(16) __half g_uh [(size_t)BN * UU];    // update gate fp16
__device__ __align__(16) __half g_wfch[KP_G * 128];        // W_fc fp16; rows 66..79 stay 0
__device__ __align__(16) __half g_wgh [KP_C * 64];         // W_g fp16; rows 132..143 stay 0
__device__ int    g_cnt[NN];                               // zero on entry (restored by k_cand)
__device__ int    g_scol[NN * CAP];
__device__ float  g_sval[NN * CAP];

__device__ __forceinline__ float fsigmoid(float z) { return 1.f / (1.f + __expf(-z)); }
__device__ __forceinline__ float ftanh(float x) {
    float y; asm("tanh.approx.f32 %0, %1;" : "=f"(y) : "f"(x)); return y;
}
__device__ __forceinline__ void cp_async16(void* sdst, const void* gsrc) {
    unsigned s = (unsigned)__cvta_generic_to_shared(sdst);
    asm volatile("cp.async.cg.shared.global [%0], [%1], 16;" :: "r"(s), "l"(gsrc));
}
__device__ __forceinline__ void cp_commit() { asm volatile("cp.async.commit_group;"); }
__device__ __forceinline__ void cp_wait0()  { asm volatile("cp.async.wait_group 0;" ::: "memory"); }

// ---------------- kernel 0: edge scatter + fp16 weight conversion --------------------
__global__ void k_prep(const int* __restrict__ rows, const int* __restrict__ cols,
                       const float* __restrict__ vals,
                       const float* __restrict__ Wfc, const float* __restrict__ Wg) {
    int e = blockIdx.x * blockDim.x + threadIdx.x;
    if (e < 4224) {                     // W_fc: 66*128 = 8448 floats = 4224 float2
        float2 w = ((const float2*)Wfc)[e];
        ((__half2*)g_wfch)[e] = __floats2half2_rn(w.x, w.y);
    } else if (e < 8448) {              // W_g: 132*64 floats
        int i = e - 4224;
        float2 w = ((const float2*)Wg)[i];
        ((__half2*)g_wgh)[i] = __floats2half2_rn(w.x, w.y);
    }
    if (e < EE) {
        int r = rows[e];
        int slot = atomicAdd(&g_cnt[r], 1);
        if (slot < CAP) {
            g_scol[r * CAP + slot] = cols[e];
            g_sval[r * CAP + slot] = vals[e];
        }
    }
}

// ---------------- kernel 1: gates via HMMA; two-phase epilogue (small smem) ----------
__global__ void __launch_bounds__(256) k_gates(const float* __restrict__ inputs,
                                               const float* __restrict__ hx,
                                               const float* __restrict__ bfc) {
    extern __shared__ char smraw[];
    __half* sA   = (__half*)smraw;                        // 64 x LDA_G (preserved)
    __half* sB   = (__half*)(smraw + SA_G_BYTES);         // KP_G x LDB_G
    float*  sOut = (float*)(smraw + SA_G_BYTES);          // 32 x LDO_G (aliases sB)
    float*  sBias = (float*)(smraw + SA_G_BYTES + SB_G_BYTES);   // 128

    int tid = threadIdx.x;
    int r0 = blockIdx.x * 64;

    // sB via cp.async from pre-converted g_wfch (80 rows x 16 chunks of 16B)
#pragma unroll
    for (int i = tid; i < KP_G * 16; i += 256) {
        int k = i >> 4, c = i & 15;
        cp_async16(sB + k * LDB_G + c * 8, g_wfch + k * 128 + c * 8);
    }
    cp_commit();

    // sA rows with [inputs(2) | hx(64)] fp16; pad cols 66..79
    for (int i = tid; i < 1024; i += 256) {
        int r = i >> 4, q = i & 15;
        float4 h = ((const float4*)hx)[(size_t)(r0 + r) * 16 + q];
        int off = r * LDA_G + 2 + q * 4;
        *(__half2*)(sA + off)     = __floats2half2_rn(h.x, h.y);
        *(__half2*)(sA + off + 2) = __floats2half2_rn(h.z, h.w);
    }
    if (tid < 64) {
        float2 xin = ((const float2*)inputs)[r0 + tid];
        *(__half2*)(sA + tid * LDA_G) = __floats2half2_rn(xin.x, xin.y);
        __half2 zz = __half2half2(__float2half(0.f));
#pragma unroll
        for (int k = 66; k < KP_G; k += 2) *(__half2*)(sA + tid * LDA_G + k) = zz;
    }
    if (tid < 128) sBias[tid] = bfc[tid];
    cp_wait0();
    __syncthreads();

    // 8 warps: warp (wm, wn): m-tile wm (0..3), n-tiles wn*4 .. wn*4+3
    int wid = tid >> 5;
    int wm = wid & 3, wn = wid >> 2;
    wmma::fragment<wmma::accumulator, 16, 16, 16, float> c[4];
#pragma unroll
    for (int j = 0; j < 4; ++j) wmma::fill_fragment(c[j], 0.f);
#pragma unroll
    for (int k = 0; k < KP_G / 16; ++k) {
        wmma::fragment<wmma::matrix_a, 16, 16, 16, __half, wmma::row_major> a;
        wmma::load_matrix_sync(a, sA + wm * 16 * LDA_G + k * 16, LDA_G);
#pragma unroll
        for (int j = 0; j < 4; ++j) {
            wmma::fragment<wmma::matrix_b, 16, 16, 16, __half, wmma::row_major> b;
            wmma::load_matrix_sync(b, sB + k * 16 * LDB_G + (wn * 4 + j) * 16, LDB_G);
            wmma::mma_sync(c[j], a, b, c[j]);
        }
    }

    // two-phase epilogue: phase p handles rows p*32 .. p*32+31 (sOut = 32 rows)
#pragma unroll
    for (int p = 0; p < 2; ++p) {
        __syncthreads();   // sOut region free (sB dead after MMA / prev phase done)
        if ((wm >> 1) == p) {
            int rloc = (wm & 1) * 16;
#pragma unroll
            for (int j = 0; j < 4; ++j)
                wmma::store_matrix_sync(sOut + rloc * LDO_G + (wn * 4 + j) * 16, c[j],
                                        LDO_G, wmma::mem_row_major);
        }
        __syncthreads();
        for (int i = tid; i < 1024; i += 256) {
            int rl = i >> 5, q = i & 31;
            int col = q * 4;
            int r = p * 32 + rl;
            int row = r0 + r;
            float4 z = *(float4*)(sOut + rl * LDO_G + col);
            z.x = fsigmoid(z.x + sBias[col + 0]);
            z.y = fsigmoid(z.y + sBias[col + 1]);
            z.z = fsigmoid(z.z + sBias[col + 2]);
            z.w = fsigmoid(z.w + sBias[col + 3]);
            if (q < 16) {
                // hx fp16 in sA at halves offset ≡ 2 mod 4 -> two half2 loads
                __half2 h01 = *(__half2*)(sA + r * LDA_G + 2 + col);
                __half2 h23 = *(__half2*)(sA + r * LDA_G + 2 + col + 2);
                float2 ha = __half22float2(h01);
                float2 hb = __half22float2(h23);
                int n = row % NN, b = row / NN;
                size_t base = (size_t)n * BD + b * DD + 2 + col;
                *(__half2*)(g_x0h + base)     = __floats2half2_rn(z.x * ha.x, z.y * ha.y);
                *(__half2*)(g_x0h + base + 2) = __floats2half2_rn(z.z * hb.x, z.w * hb.y);
            } else {
                __half2 a = __floats2half2_rn(z.x, z.y);
                __half2 b2 = __floats2half2_rn(z.z, z.w);
                uint2 uv;
                uv.x = *(unsigned*)&a; uv.y = *(unsigned*)&b2;
                ((uint2*)g_uh)[(size_t)row * 16 + (q - 16)] = uv;
            }
        }
    }
    // x0h[n, b, 0:2] = inputs (fp16, from sA — row start is 4B-aligned half2)
    if (tid < 64) {
        int row = r0 + tid;
        int n = row % NN, b = row / NN;
        *(__half2*)(g_x0h + (size_t)n * BD + b * DD) = *(__half2*)(sA + tid * LDA_G);
    }
}

// ---------------- kernel 2: SpMM (HFMA2, 8B lanes, 1 node/block) ---------------------
// block per node n; 264 threads, one uint2 (4 halves) each. Inner loop: 6 issue slots.
__global__ void __launch_bounds__(264) k_spmm() {
    __shared__ int     s_col[CAP];
    __shared__ __half2 s_val[CAP];       // pre-splatted fp16 edge values
    int n = blockIdx.x;
    int tid = threadIdx.x;
    int cnt = min(g_cnt[n], CAP);
    if (tid < cnt) {
        s_col[tid] = g_scol[n * CAP + tid];
        s_val[tid] = __half2half2(__float2half_rn(g_sval[n * CAP + tid]));
    }
    __syncthreads();
    __half2 acc0 = __half2half2(__float2half(0.f));
    __half2 acc1 = acc0;
    const uint2* x0h8 = (const uint2*)g_x0h;   // 8B = 4 halves
    for (int i = 0; i < cnt; ++i) {
        __half2 v = s_val[i];
        int     c = s_col[i];
        uint2 raw = x0h8[(size_t)c * 264 + tid];
        acc0 = __hfma2(*(__half2*)&raw.x, v, acc0);
        acc1 = __hfma2(*(__half2*)&raw.y, v, acc1);
    }
    // own x0 row (4 halves), pack interleaved (x0[d], x1[d]) into g_cat (stride 68 half2)
    uint2 own = x0h8[(size_t)n * 264 + tid];
    __half x0e[4], x1e[4];
    *(__half2*)&x0e[0] = *(__half2*)&own.x;
    *(__half2*)&x0e[2] = *(__half2*)&own.y;
    *(__half2*)&x1e[0] = acc0;
    *(__half2*)&x1e[2] = acc1;
    __half2* cat2 = (__half2*)g_cat;
    int j0 = tid * 4;
#pragma unroll
    for (int e = 0; e < 4; ++e) {
        int j = j0 + e;
        int b = j / DD, d = j - b * DD;
        size_t row = (size_t)b * NN + n;
        cat2[row * (CATS / 2) + d] = __halves2half2(x0e[e], x1e[e]);
    }
    // zero 4-half row pad (halves 132..135)
    if (tid < 16)
        ((uint2*)g_cat)[((size_t)tid * NN + n) * (CATS / 4) + 33] = make_uint2(0u, 0u);
}

// ---------------- kernel 3: candidate GEMM via HMMA (+tanh) and GRU combine ----------
__global__ void __launch_bounds__(256) k_cand(const float* __restrict__ hx,
                                              const float* __restrict__ bg,
                                              float* __restrict__ out) {
    extern __shared__ char smraw[];
    __half* sA   = (__half*)smraw;                    // 64 x LDA_C
    __half* sB   = sA + 64 * LDA_C;                   // KP_C x LDB_C
    float*  sOut = (float*)smraw;                     // 64 x LDO_C (aliases sA/sB)
    float*  sBias = (float*)(smraw + GEMM_REG_C);     // 64

    int tid = threadIdx.x;
    int r0 = blockIdx.x * 64;

    // restore g_cnt = 0 for the next call (g_cnt already consumed by k_spmm)
    if (tid < 4) g_cnt[blockIdx.x * 4 + tid] = 0;

    // sB via cp.async from g_wgh (144 rows x 8 chunks of 16B)
#pragma unroll
    for (int i = tid; i < KP_C * 8; i += 256) {
        int k = i >> 3, c = i & 7;
        cp_async16(sB + k * LDB_C + c * 8, g_wgh + k * 64 + c * 8);
    }
    // sA via cp.async from padded g_cat (64 rows x 17 chunks of 16B)
#pragma unroll
    for (int i = tid; i < 64 * 17; i += 256) {
        int r = i / 17, dp = i - r * 17;
        cp_async16(sA + r * LDA_C + dp * 8, g_cat + (size_t)(r0 + r) * CATS + dp * 8);
    }
    cp_commit();
    if (tid < 64) {
        *(uint4*)(sA + tid * LDA_C + 136) = make_uint4(0u, 0u, 0u, 0u);  // k 136..143
        sBias[tid] = bg[tid];
    }
    cp_wait0();
    __syncthreads();

    // 8 warps: warp (wm, wn2): m-tile wm, n-tiles wn2*2 + {0,1}
    int wid = tid >> 5;
    int wm = wid & 3, wn2 = wid >> 2;
    wmma::fragment<wmma::accumulator, 16, 16, 16, float> c[2];
#pragma unroll
    for (int j = 0; j < 2; ++j) wmma::fill_fragment(c[j], 0.f);
#pragma unroll
    for (int k = 0; k < KP_C / 16; ++k) {
        wmma::fragment<wmma::matrix_a, 16, 16, 16, __half, wmma::row_major> a;
        wmma::load_matrix_sync(a, sA + wm * 16 * LDA_C + k * 16, LDA_C);
#pragma unroll
        for (int j = 0; j < 2; ++j) {
            wmma::fragment<wmma::matrix_b, 16, 16, 16, __half, wmma::row_major> b;
            wmma::load_matrix_sync(b, sB + k * 16 * LDB_C + (wn2 * 2 + j) * 16, LDB_C);
            wmma::mma_sync(c[j], a, b, c[j]);
        }
    }
    __syncthreads();   // sOut aliases sA/sB
#pragma unroll
    for (int j = 0; j < 2; ++j)
        wmma::store_matrix_sync(sOut + wm * 16 * LDO_C + (wn2 * 2 + j) * 16, c[j],
                                LDO_C, wmma::mem_row_major);
    __syncthreads();

    // epilogue: tanh.approx + GRU combine, vectorized float4
    for (int i = tid; i < 1024; i += 256) {
        int r = i >> 4, q = i & 15;
        int col = q * 4;
        int row = r0 + r;
        float4 z = *(float4*)(sOut + r * LDO_C + col);
        z.x = ftanh(z.x + sBias[col + 0]);
        z.y = ftanh(z.y + sBias[col + 1]);
        z.z = ftanh(z.z + sBias[col + 2]);
        z.w = ftanh(z.w + sBias[col + 3]);
        size_t o = (size_t)row * 16 + q;
        uint2 uv = ((const uint2*)g_uh)[o];
        float2 ua = __half22float2(*(__half2*)&uv.x);
        float2 ub = __half22float2(*(__half2*)&uv.y);
        float4 h4 = ((const float4*)hx)[o];
        float4 res;
        res.x = ua.x * h4.x + (1.f - ua.x) * z.x;
        res.y = ua.y * h4.y + (1.f - ua.y) * z.y;
        res.z = ub.x * h4.z + (1.f - ub.x) * z.z;
        res.w = ub.y * h4.w + (1.f - ub.y) * z.w;
        ((float4*)out)[o] = res;
    }
}

// ---------------- launcher ----------------
extern "C" void kernel_launch(void* const* d_in, const int* in_sizes, int n_in,
                              void* d_out, int out_size) {
    (void)in_sizes; (void)n_in; (void)out_size;
    const float* inputs = (const float*)d_in[0];
    const float* hx     = (const float*)d_in[1];
    const int*   rows   = (const int*)d_in[2];
    const int*   cols   = (const int*)d_in[3];
    const float* vals   = (const float*)d_in[4];
    const float* Wfc    = (const float*)d_in[5];
    const float* bfc    = (const float*)d_in[6];
    const float* Wg     = (const float*)d_in[7];
    const float* bg     = (const float*)d_in[8];
    float* out = (float*)d_out;

    cudaFuncSetAttribute(k_gates, cudaFuncAttributeMaxDynamicSharedMemorySize, SMEM_G);
    cudaFuncSetAttribute(k_cand,  cudaFuncAttributeMaxDynamicSharedMemorySize, SMEM_C);

    k_prep<<<(EE + 255) / 256, 256>>>(rows, cols, vals, Wfc, Wg);
    k_gates<<<BN / 64, 256, SMEM_G>>>(inputs, hx, bfc);
    k_spmm<<<NN, 264>>>();
    k_cand<<<BN / 64, 256, SMEM_C>>>(hx, bg, out);
}